// round 15
// baseline (speedup 1.0000x reference)
#include <cuda_runtime.h>
#include <math.h>

// ProLiF fused SIREN MLP, fp32, sm_103a — f32x2, 3 CTA/SM, lite df-sine,
// pre-duplicated u64 weight buffer (R15).
// Shapes (fixed): B=65536, N=16, C=32, H=64, O=4, MID=4.
//
// Numerics contract (PASS R9-R14): reproduce jax/XLA:CPU (glibc sincosf):
// ascending-k single-accumulator FMA chains (bitwise), one fp32 bias add,
// one fp32 mul by 30, glibc sine algorithm in float-float (abs err ~1e-12).
// R15 changes NO arithmetic: weights are stored in smem as {w,w} u64 pairs
// so GEMM b-operands load lane-replicated directly (kills 512 MOVs/layer).

#define NF 16
#define CI 32
#define HD 64
#define OD 4
#define NMID 4

#define TILE_B   128
#define NPAIR    64
#define NTHREADS 256
#define H2STRIDE 66          // u64 row stride for h2 (pad 2)
#define W2STRIDE 66          // u64 row stride for wt2 (pad 2)

typedef unsigned long long u64;

// ---------------- f32x2 primitives (inline PTX, sm_100+) ----------------
__device__ __forceinline__ u64 pk2(float lo, float hi) {
    u64 r;
    asm("mov.b64 %0, {%1, %2};" : "=l"(r)
        : "r"(__float_as_uint(lo)), "r"(__float_as_uint(hi)));
    return r;
}
__device__ __forceinline__ u64 dupf(float v) { return pk2(v, v); }
__device__ __forceinline__ u64 addx2(u64 a, u64 b) {
    u64 d; asm("add.rn.f32x2 %0, %1, %2;" : "=l"(d) : "l"(a), "l"(b)); return d;
}
__device__ __forceinline__ u64 subx2(u64 a, u64 b) {
    u64 d; asm("sub.rn.f32x2 %0, %1, %2;" : "=l"(d) : "l"(a), "l"(b)); return d;
}
__device__ __forceinline__ u64 mulx2(u64 a, u64 b) {
    u64 d; asm("mul.rn.f32x2 %0, %1, %2;" : "=l"(d) : "l"(a), "l"(b)); return d;
}
__device__ __forceinline__ u64 fmax2(u64 a, u64 b, u64 c) {
    u64 d; asm("fma.rn.f32x2 %0, %1, %2, %3;" : "=l"(d) : "l"(a), "l"(b), "l"(c)); return d;
}
__device__ __forceinline__ u64 negx2(u64 a) { return a ^ 0x8000000080000000ULL; }
// per-lane select: m all-ones lanes take a, zero lanes take b
__device__ __forceinline__ u64 sel64(u64 a, u64 b, u64 m) {
    return (a & m) | (b & ~m);
}

struct dfx { u64 h, l; };
__device__ __forceinline__ dfx fast2sum_x2(u64 a, u64 b) {  // |a| >= |b| /lane
    u64 s = addx2(a, b);
    u64 e = addx2(subx2(a, s), b);
    dfx r; r.h = s; r.l = e; return r;
}

// ---- glibc sincosf table (sysdeps/ieee754/flt-32/sincosf.h), exact ----
#define GS_HPI_INV 0x1.45F306DC9C883p-1
#define GS_HPI     0x1.921FB54442D18p0
#define GS_S1 (-0x1.555545995770dp-3)
#define GS_S2 ( 0x1.1107605230bc4p-7)
#define GS_S3 (-0x1.994eb3774cf24p-13)
#define GS_C1 (-0x1.ffffffd0c621cp-2)
#define GS_C2 ( 0x1.55553e1068f19p-5)
#define GS_C3 (-0x1.6c087e89a359dp-10)
#define GS_C4 ( 0x1.99343027bf8c3p-16)

#define FHI(d) ((float)(d))
#define FLO(d) ((float)((d) - (double)(float)(d)))

// glibc-sinf replica, lite float-float (identical sequence to R14).
__device__ __forceinline__ u64 glibc_sinf_lite_x2(u64 y) {
    const u64 IH    = dupf((float)GS_HPI_INV);
    const u64 MAGIC = dupf(12582912.0f);          // 2^23 + 2^22
    const u64 H1 = dupf(FHI(GS_HPI));
    const u64 H2 = dupf(FLO(GS_HPI));

    // ---- quadrant: RNE integer via magic add; n mod 4 in low bits ----
    u64 ph = mulx2(y, IH);
    u64 tq = addx2(ph, MAGIC);
    unsigned u0 = (unsigned)tq;
    unsigned u1 = (unsigned)(tq >> 32);
    u64 nf = subx2(tq, MAGIC);

    // ---- reduction: r = y - nf*pi/2 (df-lite) ----
    u64 q1 = mulx2(nf, H1);
    u64 e1 = fmax2(nf, H1, negx2(q1));            // exact residual
    u64 r0 = subx2(y, q1);                        // exact (Sterbenz)
    u64 c  = fmax2(nf, H2, e1);                   // e1 + nf*h2 (1 rounding)
    dfx r  = fast2sum_x2(r0, negx2(c));

    // ---- x2 = r*r (df) ----
    u64 x2h = mulx2(r.h, r.h);
    u64 x2t = fmax2(r.h, r.h, negx2(x2h));
    u64 x2l = fmax2(addx2(r.h, r.h), r.l, x2t);

    // ---- branch masks (odd lanes -> cos poly) ----
    u64 m = ((u0 & 1u) ? 0x00000000FFFFFFFFULL : 0ULL)
          | ((u1 & 1u) ? 0xFFFFFFFF00000000ULL : 0ULL);
    u64 sg = ((u64)((u1 & 2u) << 30) << 32) | (u64)((u0 & 2u) << 30);

    // ---- step1: a = C3 + x2*C4 (cos) / S3 (sin), with residual ----
    const u64 C4h = dupf(FHI(GS_C4));
    const u64 C3h = dupf(FHI(GS_C3)), C3l = dupf(FLO(GS_C3));
    const u64 S3h = dupf(FHI(GS_S3)), S3l = dupf(FLO(GS_S3));
    u64 I1 = fmax2(x2h, C4h, C3h);
    u64 eI = fmax2(x2h, C4h, subx2(C3h, I1));     // residual (sub exact)
    u64 ah = sel64(I1, S3h, m);
    u64 al = sel64(addx2(eI, C3l), S3l, m);

    // ---- step2: t2 = K2 + x2*a ----
    u64 K2h = sel64(dupf(FHI(GS_C2)), dupf(FHI(GS_S2)), m);
    u64 K2l = sel64(dupf(FLO(GS_C2)), dupf(FLO(GS_S2)), m);
    u64 p2 = mulx2(ah, x2h);
    u64 e2 = fmax2(ah, x2h, negx2(p2));
    e2 = fmax2(ah, x2l, e2);
    e2 = fmax2(al, x2h, e2);
    dfx t2 = fast2sum_x2(K2h, p2);                // |K2| >= |p2| per lane
    u64 t2l = addx2(t2.l, addx2(e2, K2l));

    // ---- step3: t3 = K1 + x2*t2 ----
    u64 K1h = sel64(dupf(FHI(GS_C1)), dupf(FHI(GS_S1)), m);
    u64 K1l = sel64(dupf(FLO(GS_C1)), dupf(FLO(GS_S1)), m);
    u64 p3 = mulx2(t2.h, x2h);
    u64 e3 = fmax2(t2.h, x2h, negx2(p3));
    e3 = fmax2(t2.h, x2l, e3);
    e3 = fmax2(t2l, x2h, e3);
    dfx t3 = fast2sum_x2(K1h, p3);                // |K1| >= |p3| per lane
    u64 t3l = addx2(t3.l, addx2(e3, K1l));

    // ---- step4: Q = 1 + x2*t3 ----
    u64 p4 = mulx2(t3.h, x2h);
    u64 e4 = fmax2(t3.h, x2h, negx2(p4));
    e4 = fmax2(t3.h, x2l, e4);
    e4 = fmax2(t3l, x2h, e4);
    dfx Q = fast2sum_x2(dupf(1.0f), p4);          // |p4| <= 0.32 < 1
    u64 Ql = addx2(Q.l, e4);

    // ---- finals ----
    u64 sh = mulx2(r.h, Q.h);
    u64 se = fmax2(r.h, Q.h, negx2(sh));
    se = fmax2(r.h, Ql, se);
    se = fmax2(r.l, Q.h, se);
    u64 sinv = addx2(sh, se);
    u64 cosv = addx2(Q.h, Ql);

    return sel64(cosv, sinv, m) ^ sg;
}

__device__ __forceinline__ u64 act_sine_x2(u64 acc, u64 bias2) {
    u64 t = addx2(acc, bias2);             // per-lane __fadd_rn
    u64 u = mulx2(dupf(30.0f), t);         // per-lane __fmul_rn
    return glibc_sinf_lite_x2(u);
}

struct SmemLayout {
    u64   h2[NPAIR][H2STRIDE];      // 33792 B: h2[p][k] = {h[2p][k], h[2p+1][k]}
    u64   wt2[HD][W2STRIDE];        // 33792 B: wt2[k][j] = {w[j][k], w[j][k]}
    float wl[OD][HD];
    float b0s[HD];
    float bms[NMID][HD];
    float bls[OD];
};

// One dense layer + sine. Thread tile: 4 row-pairs x 4 cols.
// Per-lane arithmetic: ascending k, single accumulator (bitwise contract).
template <int K>
__device__ __forceinline__ void dense_sine_layer(
    SmemLayout* s, const float* bias, int p0, int c0, int tid,
    const float* __restrict__ next_w)
{
    u64 acc[4][4];
#pragma unroll
    for (int p = 0; p < 4; p++)
#pragma unroll
        for (int q = 0; q < 4; q++) acc[p][q] = 0ULL;

#pragma unroll 4
    for (int k2 = 0; k2 < K; k2 += 2) {
        ulonglong2 a[4];
#pragma unroll
        for (int p = 0; p < 4; p++)
            a[p] = *(const ulonglong2*)&s->h2[p0 + p][k2];
        // lane-replicated weights straight from smem (no dup MOVs)
        ulonglong2 w0a = *(const ulonglong2*)&s->wt2[k2][c0];
        ulonglong2 w0b = *(const ulonglong2*)&s->wt2[k2][c0 + 2];
        ulonglong2 w1a = *(const ulonglong2*)&s->wt2[k2 + 1][c0];
        ulonglong2 w1b = *(const ulonglong2*)&s->wt2[k2 + 1][c0 + 2];
#pragma unroll
        for (int p = 0; p < 4; p++) {           // k2 (ascending chain order)
            acc[p][0] = fmax2(a[p].x, w0a.x, acc[p][0]);
            acc[p][1] = fmax2(a[p].x, w0a.y, acc[p][1]);
            acc[p][2] = fmax2(a[p].x, w0b.x, acc[p][2]);
            acc[p][3] = fmax2(a[p].x, w0b.y, acc[p][3]);
        }
#pragma unroll
        for (int p = 0; p < 4; p++) {           // k2+1
            acc[p][0] = fmax2(a[p].y, w1a.x, acc[p][0]);
            acc[p][1] = fmax2(a[p].y, w1a.y, acc[p][1]);
            acc[p][2] = fmax2(a[p].y, w1b.x, acc[p][2]);
            acc[p][3] = fmax2(a[p].y, w1b.y, acc[p][3]);
        }
    }

    __syncthreads();   // all reads of h2 AND wt2 done

    // ---- stage next layer's weights (duplicated), overlapped with sine ----
    if (next_w) {
#pragma unroll
        for (int t = 0; t < (HD * HD) / NTHREADS; t++) {
            int idx = tid + t * NTHREADS;
            int j = idx >> 6, k = idx & 63;     // gmem-coalesced in k
            float w = next_w[idx];
            s->wt2[k][j] = pk2(w, w);
        }
    }

    // ---- sine + writeback ----
    u64 bb0 = dupf(bias[c0 + 0]), bb1 = dupf(bias[c0 + 1]);
    u64 bb2 = dupf(bias[c0 + 2]), bb3 = dupf(bias[c0 + 3]);
#pragma unroll 1
    for (int p = 0; p < 4; p++) {
        ulonglong2 s01, s23;
        s01.x = act_sine_x2(acc[p][0], bb0);
        s01.y = act_sine_x2(acc[p][1], bb1);
        s23.x = act_sine_x2(acc[p][2], bb2);
        s23.y = act_sine_x2(acc[p][3], bb3);
        *(ulonglong2*)&s->h2[p0 + p][c0]     = s01;
        *(ulonglong2*)&s->h2[p0 + p][c0 + 2] = s23;
    }
    __syncthreads();
}

extern __shared__ float smem_raw[];

__global__ void __launch_bounds__(NTHREADS, 3) prolif_kernel(
    const float* __restrict__ emb,
    const float* __restrict__ W0,
    const float* __restrict__ b0,
    const float* __restrict__ Wmid,
    const float* __restrict__ bmid,
    const float* __restrict__ Wlast,
    const float* __restrict__ blast,
    float* __restrict__ out)
{
    SmemLayout* s = (SmemLayout*)smem_raw;
    const int n    = blockIdx.y;
    const int row0 = blockIdx.x * TILE_B;
    const int tid  = threadIdx.x;

    // ---- stage layer-0 weights (transposed + duplicated), biases, last ----
    for (int idx = tid; idx < HD * CI; idx += NTHREADS) {
        int j = idx / CI, k = idx % CI;
        float w = W0[n * HD * CI + idx];
        s->wt2[k][j] = pk2(w, w);
    }
    for (int idx = tid; idx < OD * HD; idx += NTHREADS)
        ((float*)s->wl)[idx] = Wlast[n * OD * HD + idx];
    for (int idx = tid; idx < HD; idx += NTHREADS)
        s->b0s[idx] = b0[n * HD + idx];
#pragma unroll 1
    for (int i = 0; i < NMID; i++)
        for (int idx = tid; idx < HD; idx += NTHREADS)
            s->bms[i][idx] = bmid[(i * NF + n) * HD + idx];
    for (int idx = tid; idx < OD; idx += NTHREADS)
        s->bls[idx] = blast[n * OD + idx];

    // ---- stage x tile into h2[:, 0..31] as row pairs ----
    for (int idx = tid; idx < NPAIR * CI; idx += NTHREADS) {
        int p = idx >> 5, cc = idx & 31;
        const float* base = emb + (size_t)(row0 + 2 * p) * (NF * CI) + n * CI + cc;
        s->h2[p][cc] = pk2(base[0], base[NF * CI]);
    }
    __syncthreads();

    const int tr = tid >> 4;
    const int tc = tid & 15;
    const int p0 = tr * 4;
    const int c0 = tc * 4;

    // ---- layer 0 (32->64), staging Wmid[0] during its sine phase ----
    dense_sine_layer<CI>(s, s->b0s, p0, c0, tid,
                         Wmid + (size_t)(0 * NF + n) * HD * HD);

    // ---- mid layers (64->64); layer i stages Wmid[i+1] ----
#pragma unroll 1
    for (int i = 0; i < NMID; i++) {
        const float* nxt = (i + 1 < NMID)
            ? (Wmid + (size_t)((i + 1) * NF + n) * HD * HD) : (const float*)0;
        dense_sine_layer<HD>(s, s->bms[i], p0, c0, tid, nxt);
    }

    // ---- last layer: 64 -> 4, no activation ----
    {
        const int lrow = tid & (TILE_B - 1);
        const int og   = (tid >> 7) << 1;
        const float* w0r = s->wl[og];
        const float* w1r = s->wl[og + 1];
        const float* rowb = (const float*)&s->h2[lrow >> 1][0];
        const int lane = lrow & 1;
        float a0 = 0.0f, a1 = 0.0f;
#pragma unroll
        for (int j = 0; j < HD; j += 2) {
            float4 v = *(const float4*)(rowb + 2 * j);
            float hj  = lane ? v.y : v.x;
            float hj1 = lane ? v.w : v.z;
            a0 = fmaf(hj,  w0r[j],     a0);
            a0 = fmaf(hj1, w0r[j + 1], a0);
            a1 = fmaf(hj,  w1r[j],     a1);
            a1 = fmaf(hj1, w1r[j + 1], a1);
        }
        a0 = __fadd_rn(a0, s->bls[og]);
        a1 = __fadd_rn(a1, s->bls[og + 1]);
        float2 o2 = make_float2(a0, a1);
        *(float2*)&out[(size_t)(row0 + lrow) * (NF * OD) + n * OD + og] = o2;
    }
}

extern "C" void kernel_launch(void* const* d_in, const int* in_sizes, int n_in,
                              void* d_out, int out_size) {
    const float* emb   = (const float*)d_in[0];
    const float* W0    = (const float*)d_in[1];
    const float* b0    = (const float*)d_in[2];
    const float* Wmid  = (const float*)d_in[3];
    const float* bmid  = (const float*)d_in[4];
    const float* Wlast = (const float*)d_in[5];
    const float* blast = (const float*)d_in[6];
    float* out = (float*)d_out;

    const int B = in_sizes[0] / (NF * CI);   // 65536

    cudaFuncSetAttribute(prolif_kernel,
                         cudaFuncAttributeMaxDynamicSharedMemorySize,
                         (int)sizeof(SmemLayout));

    dim3 grid(B / TILE_B, NF);
    prolif_kernel<<<grid, NTHREADS, sizeof(SmemLayout)>>>(
        emb, W0, b0, Wmid, bmid, Wlast, blast, out);
}

// round 17
// speedup vs baseline: 1.4067x; 1.4067x over previous
#include <cuda_runtime.h>
#include <math.h>

// ProLiF fused SIREN MLP, fp32, sm_103a — f32x2, 3 CTA/SM, audited slim sine.
// Shapes (fixed): B=65536, N=16, C=32, H=64, O=4, MID=4.
//
// Numerics contract (PASS R9-R15): reproduce jax/XLA:CPU (glibc sincosf):
// ascending-k single-accumulator FMA chains (bitwise), one fp32 bias add,
// one fp32 mul by 30, glibc sine algorithm in float-float.
// R17 sine = R14 lite sine with ONLY audited-safe trims (each dropped term
// <= ~3e-12 rms effect after x2-power attenuation; budget 1e-11):
//   step1 pure f32; step2 keeps product residual + K2 low word, drops the
//   two x2l/al cross terms. Steps 3/4/finals identical to R14 (PASS 4e-5).

#define NF 16
#define CI 32
#define HD 64
#define OD 4
#define NMID 4

#define TILE_B   128
#define NPAIR    64
#define NTHREADS 256
#define H2STRIDE 66          // u64 row stride for h2 (pad 2)
#define WSTRIDE  68          // float row stride for wt (pad 4)

typedef unsigned long long u64;

// ---------------- f32x2 primitives (inline PTX, sm_100+) ----------------
__device__ __forceinline__ u64 pk2(float lo, float hi) {
    u64 r;
    asm("mov.b64 %0, {%1, %2};" : "=l"(r)
        : "r"(__float_as_uint(lo)), "r"(__float_as_uint(hi)));
    return r;
}
__device__ __forceinline__ u64 dupf(float v) { return pk2(v, v); }
__device__ __forceinline__ u64 addx2(u64 a, u64 b) {
    u64 d; asm("add.rn.f32x2 %0, %1, %2;" : "=l"(d) : "l"(a), "l"(b)); return d;
}
__device__ __forceinline__ u64 subx2(u64 a, u64 b) {
    u64 d; asm("sub.rn.f32x2 %0, %1, %2;" : "=l"(d) : "l"(a), "l"(b)); return d;
}
__device__ __forceinline__ u64 mulx2(u64 a, u64 b) {
    u64 d; asm("mul.rn.f32x2 %0, %1, %2;" : "=l"(d) : "l"(a), "l"(b)); return d;
}
__device__ __forceinline__ u64 fmax2(u64 a, u64 b, u64 c) {
    u64 d; asm("fma.rn.f32x2 %0, %1, %2, %3;" : "=l"(d) : "l"(a), "l"(b), "l"(c)); return d;
}
__device__ __forceinline__ u64 negx2(u64 a) { return a ^ 0x8000000080000000ULL; }
__device__ __forceinline__ u64 sel64(u64 a, u64 b, u64 m) {
    return (a & m) | (b & ~m);
}

struct dfx { u64 h, l; };
__device__ __forceinline__ dfx fast2sum_x2(u64 a, u64 b) {  // |a| >= |b| /lane
    u64 s = addx2(a, b);
    u64 e = addx2(subx2(a, s), b);
    dfx r; r.h = s; r.l = e; return r;
}

// ---- glibc sincosf table (sysdeps/ieee754/flt-32/sincosf.h), exact ----
#define GS_HPI_INV 0x1.45F306DC9C883p-1
#define GS_HPI     0x1.921FB54442D18p0
#define GS_S1 (-0x1.555545995770dp-3)
#define GS_S2 ( 0x1.1107605230bc4p-7)
#define GS_S3 (-0x1.994eb3774cf24p-13)
#define GS_C1 (-0x1.ffffffd0c621cp-2)
#define GS_C2 ( 0x1.55553e1068f19p-5)
#define GS_C3 (-0x1.6c087e89a359dp-10)
#define GS_C4 ( 0x1.99343027bf8c3p-16)

#define FHI(d) ((float)(d))
#define FLO(d) ((float)((d) - (double)(float)(d)))

// glibc-sinf replica, audited slim float-float (abs err ~3e-12 rms added
// over the R14 lite pipeline).
__device__ __forceinline__ u64 glibc_sinf_slim_x2(u64 y) {
    const u64 IH    = dupf((float)GS_HPI_INV);
    const u64 MAGIC = dupf(12582912.0f);          // 2^23 + 2^22
    const u64 H1 = dupf(FHI(GS_HPI));
    const u64 H2 = dupf(FLO(GS_HPI));

    // ---- quadrant: RNE integer via magic add; n mod 4 in low bits ----
    u64 ph = mulx2(y, IH);
    u64 tq = addx2(ph, MAGIC);
    unsigned u0 = (unsigned)tq;
    unsigned u1 = (unsigned)(tq >> 32);
    u64 nf = subx2(tq, MAGIC);

    // ---- reduction: r = y - nf*pi/2 (df-lite, identical to R14) ----
    u64 q1 = mulx2(nf, H1);
    u64 e1 = fmax2(nf, H1, negx2(q1));            // exact residual
    u64 r0 = subx2(y, q1);                        // exact (Sterbenz)
    u64 c  = fmax2(nf, H2, e1);                   // e1 + nf*h2 (1 rounding)
    dfx r  = fast2sum_x2(r0, negx2(c));

    // ---- x2 = r*r (df) ----
    u64 x2h = mulx2(r.h, r.h);
    u64 x2t = fmax2(r.h, r.h, negx2(x2h));
    u64 x2l = fmax2(addx2(r.h, r.h), r.l, x2t);

    // ---- branch masks (odd lanes -> cos poly) ----
    u64 m = ((u0 & 1u) ? 0x00000000FFFFFFFFULL : 0ULL)
          | ((u1 & 1u) ? 0xFFFFFFFF00000000ULL : 0ULL);
    u64 sg = ((u64)((u1 & 2u) << 30) << 32) | (u64)((u0 & 2u) << 30);

    // ---- step1 (pure f32, audited): a = C3 + x2*C4 (cos) | S3 (sin) ----
    u64 ah = sel64(fmax2(x2h, dupf(FHI(GS_C4)), dupf(FHI(GS_C3))),
                   dupf(FHI(GS_S3)), m);

    // ---- step2 (df, keeps product residual + K2 low word) ----
    u64 K2h = sel64(dupf(FHI(GS_C2)), dupf(FHI(GS_S2)), m);
    u64 K2l = sel64(dupf(FLO(GS_C2)), dupf(FLO(GS_S2)), m);
    u64 p2 = mulx2(ah, x2h);
    u64 e2 = fmax2(ah, x2h, negx2(p2));           // exact product residual
    dfx t2 = fast2sum_x2(K2h, p2);                // |K2| >= |p2| per lane
    u64 t2l = addx2(t2.l, addx2(e2, K2l));

    // ---- step3 (full df, identical to R14) ----
    u64 K1h = sel64(dupf(FHI(GS_C1)), dupf(FHI(GS_S1)), m);
    u64 K1l = sel64(dupf(FLO(GS_C1)), dupf(FLO(GS_S1)), m);
    u64 p3 = mulx2(t2.h, x2h);
    u64 e3 = fmax2(t2.h, x2h, negx2(p3));
    e3 = fmax2(t2.h, x2l, e3);
    e3 = fmax2(t2l, x2h, e3);
    dfx t3 = fast2sum_x2(K1h, p3);                // |K1| >= |p3| per lane
    u64 t3l = addx2(t3.l, addx2(e3, K1l));

    // ---- step4 (full df, identical to R14) ----
    u64 p4 = mulx2(t3.h, x2h);
    u64 e4 = fmax2(t3.h, x2h, negx2(p4));
    e4 = fmax2(t3.h, x2l, e4);
    e4 = fmax2(t3l, x2h, e4);
    dfx Q = fast2sum_x2(dupf(1.0f), p4);          // |p4| <= 0.32 < 1
    u64 Ql = addx2(Q.l, e4);

    // ---- finals (identical to R14) ----
    u64 sh = mulx2(r.h, Q.h);
    u64 se = fmax2(r.h, Q.h, negx2(sh));
    se = fmax2(r.h, Ql, se);
    se = fmax2(r.l, Q.h, se);
    u64 sinv = addx2(sh, se);
    u64 cosv = addx2(Q.h, Ql);

    return sel64(cosv, sinv, m) ^ sg;
}

__device__ __forceinline__ u64 act_sine_x2(u64 acc, u64 bias2) {
    u64 t = addx2(acc, bias2);             // per-lane __fadd_rn
    u64 u = mulx2(dupf(30.0f), t);         // per-lane __fmul_rn
    return glibc_sinf_slim_x2(u);
}

struct SmemLayout {
    u64   h2[NPAIR][H2STRIDE];      // h2[p][k] = {h[2p][k], h[2p+1][k]}
    float wt[HD][WSTRIDE];          // rotating weight buffer, wt[k][j]
    float wl[OD][HD];
    float b0s[HD];
    float bms[NMID][HD];
    float bls[OD];
};

// One dense layer + sine. Thread tile: 4 row-pairs x 4 cols.
// Per-lane arithmetic: ascending k, single accumulator (bitwise contract).
template <int K>
__device__ __forceinline__ void dense_sine_layer(
    SmemLayout* s, const float* bias, int p0, int c0, int tid,
    const float* __restrict__ next_w)
{
    u64 acc[4][4];
#pragma unroll
    for (int p = 0; p < 4; p++)
#pragma unroll
        for (int q = 0; q < 4; q++) acc[p][q] = 0ULL;

#pragma unroll 4
    for (int k2 = 0; k2 < K; k2 += 2) {
        ulonglong2 a[4];
#pragma unroll
        for (int p = 0; p < 4; p++)
            a[p] = *(const ulonglong2*)&s->h2[p0 + p][k2];
        float4 w0 = *(const float4*)&s->wt[k2][c0];
        float4 w1 = *(const float4*)&s->wt[k2 + 1][c0];
        u64 w00 = dupf(w0.x), w01 = dupf(w0.y), w02 = dupf(w0.z), w03 = dupf(w0.w);
        u64 w10 = dupf(w1.x), w11 = dupf(w1.y), w12 = dupf(w1.z), w13 = dupf(w1.w);
#pragma unroll
        for (int p = 0; p < 4; p++) {           // k2 (ascending chain order)
            acc[p][0] = fmax2(a[p].x, w00, acc[p][0]);
            acc[p][1] = fmax2(a[p].x, w01, acc[p][1]);
            acc[p][2] = fmax2(a[p].x, w02, acc[p][2]);
            acc[p][3] = fmax2(a[p].x, w03, acc[p][3]);
        }
#pragma unroll
        for (int p = 0; p < 4; p++) {           // k2+1
            acc[p][0] = fmax2(a[p].y, w10, acc[p][0]);
            acc[p][1] = fmax2(a[p].y, w11, acc[p][1]);
            acc[p][2] = fmax2(a[p].y, w12, acc[p][2]);
            acc[p][3] = fmax2(a[p].y, w13, acc[p][3]);
        }
    }

    __syncthreads();   // all reads of h2 AND wt done

    // ---- stage next layer's weights (overlapped with sine compute) ----
    if (next_w) {
        float* wtf = &s->wt[0][0];
#pragma unroll
        for (int t = 0; t < (HD * HD) / NTHREADS; t++) {
            int idx = tid + t * NTHREADS;
            int j = idx >> 6, k = idx & 63;     // gmem-coalesced in k
            wtf[k * WSTRIDE + j] = next_w[idx];
        }
    }

    // ---- sine + writeback ----
    u64 bb0 = dupf(bias[c0 + 0]), bb1 = dupf(bias[c0 + 1]);
    u64 bb2 = dupf(bias[c0 + 2]), bb3 = dupf(bias[c0 + 3]);
#pragma unroll 1
    for (int p = 0; p < 4; p++) {
        ulonglong2 s01, s23;
        s01.x = act_sine_x2(acc[p][0], bb0);
        s01.y = act_sine_x2(acc[p][1], bb1);
        s23.x = act_sine_x2(acc[p][2], bb2);
        s23.y = act_sine_x2(acc[p][3], bb3);
        *(ulonglong2*)&s->h2[p0 + p][c0]     = s01;
        *(ulonglong2*)&s->h2[p0 + p][c0 + 2] = s23;
    }
    __syncthreads();
}

extern __shared__ float smem_raw[];

__global__ void __launch_bounds__(NTHREADS, 3) prolif_kernel(
    const float* __restrict__ emb,
    const float* __restrict__ W0,
    const float* __restrict__ b0,
    const float* __restrict__ Wmid,
    const float* __restrict__ bmid,
    const float* __restrict__ Wlast,
    const float* __restrict__ blast,
    float* __restrict__ out)
{
    SmemLayout* s = (SmemLayout*)smem_raw;
    const int n    = blockIdx.y;
    const int row0 = blockIdx.x * TILE_B;
    const int tid  = threadIdx.x;

    // ---- stage layer-0 weights (transposed), biases, last weights ----
    for (int idx = tid; idx < HD * CI; idx += NTHREADS) {
        int j = idx / CI, k = idx % CI;
        s->wt[k][j] = W0[n * HD * CI + idx];
    }
    for (int idx = tid; idx < OD * HD; idx += NTHREADS)
        ((float*)s->wl)[idx] = Wlast[n * OD * HD + idx];
    for (int idx = tid; idx < HD; idx += NTHREADS)
        s->b0s[idx] = b0[n * HD + idx];
#pragma unroll 1
    for (int i = 0; i < NMID; i++)
        for (int idx = tid; idx < HD; idx += NTHREADS)
            s->bms[i][idx] = bmid[(i * NF + n) * HD + idx];
    for (int idx = tid; idx < OD; idx += NTHREADS)
        s->bls[idx] = blast[n * OD + idx];

    // ---- stage x tile into h2[:, 0..31] as row pairs ----
    for (int idx = tid; idx < NPAIR * CI; idx += NTHREADS) {
        int p = idx >> 5, cc = idx & 31;
        const float* base = emb + (size_t)(row0 + 2 * p) * (NF * CI) + n * CI + cc;
        s->h2[p][cc] = pk2(base[0], base[NF * CI]);
    }
    __syncthreads();

    const int tr = tid >> 4;
    const int tc = tid & 15;
    const int p0 = tr * 4;
    const int c0 = tc * 4;

    // ---- layer 0 (32->64), staging Wmid[0] during its sine phase ----
    dense_sine_layer<CI>(s, s->b0s, p0, c0, tid,
                         Wmid + (size_t)(0 * NF + n) * HD * HD);

    // ---- mid layers (64->64); layer i stages Wmid[i+1] ----
#pragma unroll 1
    for (int i = 0; i < NMID; i++) {
        const float* nxt = (i + 1 < NMID)
            ? (Wmid + (size_t)((i + 1) * NF + n) * HD * HD) : (const float*)0;
        dense_sine_layer<HD>(s, s->bms[i], p0, c0, tid, nxt);
    }

    // ---- last layer: 64 -> 4, no activation ----
    {
        const int lrow = tid & (TILE_B - 1);
        const int og   = (tid >> 7) << 1;
        const float* w0r = s->wl[og];
        const float* w1r = s->wl[og + 1];
        const float* rowb = (const float*)&s->h2[lrow >> 1][0];
        const int lane = lrow & 1;
        float a0 = 0.0f, a1 = 0.0f;
#pragma unroll
        for (int j = 0; j < HD; j += 2) {
            float4 v = *(const float4*)(rowb + 2 * j);
            float hj  = lane ? v.y : v.x;
            float hj1 = lane ? v.w : v.z;
            a0 = fmaf(hj,  w0r[j],     a0);
            a0 = fmaf(hj1, w0r[j + 1], a0);
            a1 = fmaf(hj,  w1r[j],     a1);
            a1 = fmaf(hj1, w1r[j + 1], a1);
        }
        a0 = __fadd_rn(a0, s->bls[og]);
        a1 = __fadd_rn(a1, s->bls[og + 1]);
        float2 o2 = make_float2(a0, a1);
        *(float2*)&out[(size_t)(row0 + lrow) * (NF * OD) + n * OD + og] = o2;
    }
}

extern "C" void kernel_launch(void* const* d_in, const int* in_sizes, int n_in,
                              void* d_out, int out_size) {
    const float* emb   = (const float*)d_in[0];
    const float* W0    = (const float*)d_in[1];
    const float* b0    = (const float*)d_in[2];
    const float* Wmid  = (const float*)d_in[3];
    const float* bmid  = (const float*)d_in[4];
    const float* Wlast = (const float*)d_in[5];
    const float* blast = (const float*)d_in[6];
    float* out = (float*)d_out;

    const int B = in_sizes[0] / (NF * CI);   // 65536

    cudaFuncSetAttribute(prolif_kernel,
                         cudaFuncAttributeMaxDynamicSharedMemorySize,
                         (int)sizeof(SmemLayout));

    dim3 grid(B / TILE_B, NF);
    prolif_kernel<<<grid, NTHREADS, sizeof(SmemLayout)>>>(
        emb, W0, b0, Wmid, bmid, Wlast, blast, out);
}